// round 5
// baseline (speedup 1.0000x reference)
#include <cuda_runtime.h>
#include <cuda_bf16.h>
#include <stdint.h>

#define N_NODES 100000
#define N_EDGES 800000
#define HIDDEN  128

// ---------------- scratch (static device memory; no allocation) -------------
__device__ float g_S1[(size_t)N_NODES * HIDDEN];
__device__ float g_S2[(size_t)N_NODES * HIDDEN];
__device__ int   g_d1[N_NODES];
__device__ int   g_d2[N_NODES];

// ---------------- kernel 1: zero scratch ------------------------------------
__global__ void zero_kernel() {
    size_t tid    = (size_t)blockIdx.x * blockDim.x + threadIdx.x;
    size_t stride = (size_t)gridDim.x * blockDim.x;
    const size_t n4 = (size_t)N_NODES * HIDDEN / 4;
    float4 z = make_float4(0.f, 0.f, 0.f, 0.f);
    for (size_t j = tid; j < n4; j += stride) {
        ((float4*)g_S1)[j] = z;
        ((float4*)g_S2)[j] = z;
    }
    for (size_t j = tid; j < N_NODES; j += stride) {
        g_d1[j] = 0;
        g_d2[j] = 0;
    }
}

// ---------------- kernel 2: fused edge aggregation (one warp per edge) ------
__global__ void __launch_bounds__(256) edge_kernel(const float* __restrict__ h,
                                                   const int*   __restrict__ esrc,
                                                   const int*   __restrict__ edst) {
    int warp = (blockIdx.x * blockDim.x + threadIdx.x) >> 5;
    int lane = threadIdx.x & 31;
    if (warp >= N_EDGES) return;

    int s = esrc[warp];
    int d = edst[warp];

    float4 vd = ((const float4*)(h + (size_t)d * HIDDEN))[lane];
    float4 vs = ((const float4*)(h + (size_t)s * HIDDEN))[lane];

    atomicAdd(((float4*)(g_S1 + (size_t)s * HIDDEN)) + lane, vd);
    atomicAdd(((float4*)(g_S2 + (size_t)d * HIDDEN)) + lane, vs);

    if (lane == 0)      atomicAdd(&g_d1[s], 1);
    else if (lane == 1) atomicAdd(&g_d2[d], 1);
}

// ---------------- mma.sync helper (sm_80 baseline PTX; HMMA pipe) -----------
__device__ __forceinline__ void mma_bf16(float* d, const uint32_t* a,
                                         const uint32_t* b) {
    asm volatile(
        "mma.sync.aligned.m16n8k16.row.col.f32.bf16.bf16.f32 "
        "{%0,%1,%2,%3}, {%4,%5,%6,%7}, {%8,%9}, {%0,%1,%2,%3};"
        : "+f"(d[0]), "+f"(d[1]), "+f"(d[2]), "+f"(d[3])
        : "r"(a[0]), "r"(a[1]), "r"(a[2]), "r"(a[3]), "r"(b[0]), "r"(b[1]));
}

// ---------------- kernel 3: mma.sync bf16-split GEMM + bias + relu ----------
// out tile: 128 rows x 128 cols per block, 256 threads = 8 warps.
// warp w: rows 32*(w&3).., cols 64*(w>>2)..   (2 m-frags x 8 n-frags of 16x8)
// K loop: 12 chunks of k32 (3 sources [S1|h|S2] x 4), staged as bf16 hi/lo.
// D += Ah*Bh + Ah*Bl + Al*Bh   (lo*lo dropped; ~2^-18)
#define SA 40   // smem row stride in bf16 (32 data + 8 pad; conflict-free frags)

__global__ void __launch_bounds__(256) gemm_mma_kernel(const float* __restrict__ h,
                                                       const float* __restrict__ Ww,
                                                       const float* __restrict__ Wb,
                                                       const float* __restrict__ Wsw,
                                                       const float* __restrict__ Wsb,
                                                       const float* __restrict__ Wtw,
                                                       const float* __restrict__ Wtb,
                                                       float* __restrict__ out) {
    __shared__ __align__(16) __nv_bfloat16 Ah[128 * SA];
    __shared__ __align__(16) __nv_bfloat16 Al[128 * SA];
    __shared__ __align__(16) __nv_bfloat16 Bh[128 * SA];
    __shared__ __align__(16) __nv_bfloat16 Bl[128 * SA];

    const int tid  = threadIdx.x;
    const int wid  = tid >> 5;
    const int lid  = tid & 31;
    const int l4   = lid >> 2;          // 0..7
    const int c2   = (lid & 3) * 2;     // 0,2,4,6
    const int row0 = blockIdx.x * 128;
    const int mrow = (wid & 3) * 32;    // warp row base within tile
    const int ncol = (wid >> 2) * 64;   // warp col base within tile

    const float* Alist[3];
    Alist[0] = g_S1; Alist[1] = h; Alist[2] = g_S2;
    const float* Wlist[3];
    Wlist[0] = Ww; Wlist[1] = Wsw; Wlist[2] = Wtw;

    float acc[2][8][4];
#pragma unroll
    for (int mt = 0; mt < 2; ++mt)
#pragma unroll
        for (int nt = 0; nt < 8; ++nt)
#pragma unroll
            for (int q = 0; q < 4; ++q) acc[mt][nt][q] = 0.f;

#pragma unroll 1
    for (int ch = 0; ch < 12; ++ch) {
        const int sidx = ch >> 2;
        const int k0g  = (ch & 3) * 32;
        const float* A = Alist[sidx];
        const float* W = Wlist[sidx];

        __syncthreads();
        // ---- stage A: 128 rows x 32 k fp32 -> bf16 hi/lo ----
#pragma unroll
        for (int i = 0; i < 4; ++i) {
            int idx = tid + i * 256;       // 0..1023
            int r   = idx >> 3;            // 0..127
            int f4  = idx & 7;             // float4 group within 32 k
            float4 v = make_float4(0.f, 0.f, 0.f, 0.f);
            int grow = row0 + r;
            if (grow < N_NODES)
                v = *(const float4*)(A + (size_t)grow * HIDDEN + k0g + f4 * 4);

            float hx = __bfloat162float(__float2bfloat16_rn(v.x));
            float hy = __bfloat162float(__float2bfloat16_rn(v.y));
            float hz = __bfloat162float(__float2bfloat16_rn(v.z));
            float hw = __bfloat162float(__float2bfloat16_rn(v.w));
            __nv_bfloat162 hp0 = __floats2bfloat162_rn(v.x, v.y);
            __nv_bfloat162 hp1 = __floats2bfloat162_rn(v.z, v.w);
            __nv_bfloat162 lp0 = __floats2bfloat162_rn(v.x - hx, v.y - hy);
            __nv_bfloat162 lp1 = __floats2bfloat162_rn(v.z - hz, v.w - hw);

            uint2 hv, lv;
            hv.x = *(uint32_t*)&hp0; hv.y = *(uint32_t*)&hp1;
            lv.x = *(uint32_t*)&lp0; lv.y = *(uint32_t*)&lp1;
            *(uint2*)&Ah[r * SA + f4 * 4] = hv;
            *(uint2*)&Al[r * SA + f4 * 4] = lv;
        }
        // ---- stage B (W[n][k]): 128 n x 32 k ----
#pragma unroll
        for (int i = 0; i < 4; ++i) {
            int idx = tid + i * 256;
            int r   = idx >> 3;            // n
            int f4  = idx & 7;
            float4 v = *(const float4*)(W + (size_t)r * HIDDEN + k0g + f4 * 4);

            float hx = __bfloat162float(__float2bfloat16_rn(v.x));
            float hy = __bfloat162float(__float2bfloat16_rn(v.y));
            float hz = __bfloat162float(__float2bfloat16_rn(v.z));
            float hw = __bfloat162float(__float2bfloat16_rn(v.w));
            __nv_bfloat162 hp0 = __floats2bfloat162_rn(v.x, v.y);
            __nv_bfloat162 hp1 = __floats2bfloat162_rn(v.z, v.w);
            __nv_bfloat162 lp0 = __floats2bfloat162_rn(v.x - hx, v.y - hy);
            __nv_bfloat162 lp1 = __floats2bfloat162_rn(v.z - hz, v.w - hw);

            uint2 hv, lv;
            hv.x = *(uint32_t*)&hp0; hv.y = *(uint32_t*)&hp1;
            lv.x = *(uint32_t*)&lp0; lv.y = *(uint32_t*)&lp1;
            *(uint2*)&Bh[r * SA + f4 * 4] = hv;
            *(uint2*)&Bl[r * SA + f4 * 4] = lv;
        }
        __syncthreads();

        // ---- compute: 2 k16 steps ----
#pragma unroll
        for (int ks = 0; ks < 2; ++ks) {
            const int kf = ks * 16;
            uint32_t ah[2][4], al[2][4];
#pragma unroll
            for (int mt = 0; mt < 2; ++mt) {
                int rb = mrow + mt * 16 + l4;
                ah[mt][0] = *(const uint32_t*)&Ah[(rb)     * SA + kf + c2];
                ah[mt][1] = *(const uint32_t*)&Ah[(rb + 8) * SA + kf + c2];
                ah[mt][2] = *(const uint32_t*)&Ah[(rb)     * SA + kf + c2 + 8];
                ah[mt][3] = *(const uint32_t*)&Ah[(rb + 8) * SA + kf + c2 + 8];
                al[mt][0] = *(const uint32_t*)&Al[(rb)     * SA + kf + c2];
                al[mt][1] = *(const uint32_t*)&Al[(rb + 8) * SA + kf + c2];
                al[mt][2] = *(const uint32_t*)&Al[(rb)     * SA + kf + c2 + 8];
                al[mt][3] = *(const uint32_t*)&Al[(rb + 8) * SA + kf + c2 + 8];
            }
#pragma unroll
            for (int nt = 0; nt < 8; ++nt) {
                int nb = ncol + nt * 8 + l4;
                uint32_t bh[2], bl[2];
                bh[0] = *(const uint32_t*)&Bh[nb * SA + kf + c2];
                bh[1] = *(const uint32_t*)&Bh[nb * SA + kf + c2 + 8];
                bl[0] = *(const uint32_t*)&Bl[nb * SA + kf + c2];
                bl[1] = *(const uint32_t*)&Bl[nb * SA + kf + c2 + 8];

                mma_bf16(acc[0][nt], ah[0], bh);
                mma_bf16(acc[1][nt], ah[1], bh);
                mma_bf16(acc[0][nt], ah[0], bl);
                mma_bf16(acc[1][nt], ah[1], bl);
                mma_bf16(acc[0][nt], al[0], bh);
                mma_bf16(acc[1][nt], al[1], bh);
            }
        }
    }

    // ---- epilogue: degree-scaled bias + relu, direct stores ----
#pragma unroll
    for (int mt = 0; mt < 2; ++mt) {
        int re = row0 + mrow + mt * 16 + l4;       // rows for d0,d1
        int ro = re + 8;                           // rows for d2,d3
        float f1e = 0.f, f2e = 0.f, f1o = 0.f, f2o = 0.f;
        bool oke = re < N_NODES, oko = ro < N_NODES;
        if (oke) { f1e = (float)g_d1[re]; f2e = (float)g_d2[re]; }
        if (oko) { f1o = (float)g_d1[ro]; f2o = (float)g_d2[ro]; }
#pragma unroll
        for (int nt = 0; nt < 8; ++nt) {
            int c = ncol + nt * 8 + c2;
            float2 bw = *(const float2*)(Wb  + c);
            float2 bs = *(const float2*)(Wsb + c);
            float2 bt = *(const float2*)(Wtb + c);
            if (oke) {
                float2 o;
                o.x = fmaxf(acc[mt][nt][0] + f1e * bw.x + bs.x + f2e * bt.x, 0.f);
                o.y = fmaxf(acc[mt][nt][1] + f1e * bw.y + bs.y + f2e * bt.y, 0.f);
                *(float2*)(out + (size_t)re * HIDDEN + c) = o;
            }
            if (oko) {
                float2 o;
                o.x = fmaxf(acc[mt][nt][2] + f1o * bw.x + bs.x + f2o * bt.x, 0.f);
                o.y = fmaxf(acc[mt][nt][3] + f1o * bw.y + bs.y + f2o * bt.y, 0.f);
                *(float2*)(out + (size_t)ro * HIDDEN + c) = o;
            }
        }
    }
}

// ---------------- launch -----------------------------------------------------
extern "C" void kernel_launch(void* const* d_in, const int* in_sizes, int n_in,
                              void* d_out, int out_size) {
    const float* h    = (const float*)d_in[0];
    const int*   esrc = (const int*)  d_in[1];
    const int*   edst = (const int*)  d_in[2];
    const float* Ww   = (const float*)d_in[3];
    const float* Wb   = (const float*)d_in[4];
    const float* Wsw  = (const float*)d_in[5];
    const float* Wsb  = (const float*)d_in[6];
    const float* Wtw  = (const float*)d_in[7];
    const float* Wtb  = (const float*)d_in[8];
    float* out = (float*)d_out;

    zero_kernel<<<2048, 256>>>();
    edge_kernel<<<(N_EDGES + 7) / 8, 256>>>(h, esrc, edst);
    gemm_mma_kernel<<<(N_NODES + 127) / 128, 256>>>(h, Ww, Wb, Wsw, Wsb, Wtw, Wtb, out);
}